// round 16
// baseline (speedup 1.0000x reference)
#include <cuda_runtime.h>
#include <cuda_bf16.h>
#include <cuda_fp16.h>
#include <cstdint>

// Problem constants (fixed by the reference)
#define NNODES 50000
#define NREL   4
#define NEDGES 250000
#define INF    512
#define HIDF   512
#define OUTF   256

#define NCHUNK 49          // ceil(50000/1024)

#define W_L1_SZ (512 * 512)
#define W_L2_SZ (512 * 256)
#define W_L2_OFF (5 * W_L1_SZ)
#define W_TOT (5 * W_L1_SZ + 5 * W_L2_SZ)

// -------- scratch (device globals: no allocation in kernel_launch) --------
__device__ __align__(16) __half g_Yh[(size_t)4 * NNODES * HIDF]; // 4 neighbor planes (fp16)
__device__ __align__(16) float g_H1[(size_t)NNODES * HIDF];      // layer-1 self+bias / acc
__device__ __align__(16) float g_bs1[HIDF];
__device__ __align__(16) float g_bs2[OUTF];
__device__ __align__(16) int   g_src32[NREL * NEDGES];
__device__ __align__(16) int   g_dst32[NREL * NEDGES];
__device__ __align__(16) int   g_deg[NREL * NNODES];
__device__ __align__(16) int   g_off[NREL * NNODES];
__device__ __align__(16) int   g_cursor[NREL * NNODES];
__device__ __align__(16) int   g_bsum[NREL * NCHUNK];
__device__ __align__(16) int   g_lists[NREL * NEDGES];
__device__ int g_is64;

__device__ __align__(16) __half g_Xh[(size_t)NNODES * INF];   // A layer 1 (fp16)
__device__ __align__(16) __half g_Hh[(size_t)NNODES * HIDF];  // A layer 2 (fp16)
__device__ __align__(16) __half g_W[W_TOT];                   // weight planes [K,N], fp16

// ---------------------------------------------------------------------------
// edge dtype detection
// ---------------------------------------------------------------------------
__global__ void k_detect(const unsigned* __restrict__ w) {
    if (threadIdx.x == 0 && blockIdx.x == 0) {
        unsigned acc = 0;
        for (int i = 0; i < 64; i++) acc |= w[2 * i + 1];
        g_is64 = (acc == 0) ? 1 : 0;
    }
}

// fused prep: edge convert + deg/cursor zero + X fp16 convert
__global__ void k_prep(const void* __restrict__ ps, int* __restrict__ os,
                       const void* __restrict__ pd, int* __restrict__ od,
                       int* __restrict__ deg, int* __restrict__ cursor,
                       const float* __restrict__ x, __half* __restrict__ Xh) {
    const int NE = NREL * NEDGES;
    size_t i = (size_t)blockIdx.x * blockDim.x + threadIdx.x;
    if (i < (size_t)NE) {
        if (g_is64) {
            os[i] = (int)((const long long*)ps)[i];
            od[i] = (int)((const long long*)pd)[i];
        } else {
            os[i] = ((const int*)ps)[i];
            od[i] = ((const int*)pd)[i];
        }
    }
    if (i < NREL * NNODES) { deg[i] = 0; cursor[i] = 0; }
    if (i < (size_t)NNODES * INF) {
        Xh[i] = __float2half_rn(x[i]);
    }
}

// both layers' weight prep (planes [K,N] row-major; 0=sum self), plain fp16
__global__ void k_sumsplit_all(const float* __restrict__ Ws1, const float* __restrict__ Wn1,
                               const float* __restrict__ b1,
                               const float* __restrict__ Ws2, const float* __restrict__ Wn2,
                               const float* __restrict__ b2,
                               __half* __restrict__ w,
                               float* __restrict__ bs1, float* __restrict__ bs2) {
    int i = blockIdx.x * blockDim.x + threadIdx.x;
    if (i >= W_L1_SZ) return;
    {
        float s = 0.0f;
#pragma unroll
        for (int r = 0; r < NREL; r++) s += Ws1[(size_t)r * W_L1_SZ + i];
        w[i] = __float2half_rn(s);
#pragma unroll
        for (int r = 0; r < NREL; r++)
            w[(size_t)(1 + r) * W_L1_SZ + i] =
                __float2half_rn(Wn1[(size_t)r * W_L1_SZ + i]);
    }
    if (i < W_L2_SZ) {
        float s = 0.0f;
#pragma unroll
        for (int r = 0; r < NREL; r++) s += Ws2[(size_t)r * W_L2_SZ + i];
        w[W_L2_OFF + i] = __float2half_rn(s);
#pragma unroll
        for (int r = 0; r < NREL; r++)
            w[W_L2_OFF + (size_t)(1 + r) * W_L2_SZ + i] =
                __float2half_rn(Wn2[(size_t)r * W_L2_SZ + i]);
    }
    if (i < HIDF) {
        float bb = 0.0f;
#pragma unroll
        for (int r = 0; r < NREL; r++) bb += b1[r * HIDF + i];
        bs1[i] = bb;
    }
    if (i < OUTF) {
        float bb = 0.0f;
#pragma unroll
        for (int r = 0; r < NREL; r++) bb += b2[r * OUTF + i];
        bs2[i] = bb;
    }
}

// ---------------------------------------------------------------------------
// CSR build
// ---------------------------------------------------------------------------
__global__ void k_degcount(const int* __restrict__ dst, int* __restrict__ deg) {
    int i = blockIdx.x * blockDim.x + threadIdx.x;
    if (i >= NREL * NEDGES) return;
    int r = i / NEDGES;
    atomicAdd(&deg[r * NNODES + dst[i]], 1);
}

__global__ void k_scanA(const int* __restrict__ deg, int* __restrict__ off,
                        int* __restrict__ bsum) {
    __shared__ int s[1024];
    int r = blockIdx.x / NCHUNK;
    int c = blockIdx.x % NCHUNK;
    int idx = c * 1024 + threadIdx.x;
    int v = (idx < NNODES) ? deg[r * NNODES + idx] : 0;
    s[threadIdx.x] = v;
    __syncthreads();
#pragma unroll
    for (int d = 1; d < 1024; d <<= 1) {
        int t = (threadIdx.x >= d) ? s[threadIdx.x - d] : 0;
        __syncthreads();
        s[threadIdx.x] += t;
        __syncthreads();
    }
    if (idx < NNODES) off[r * NNODES + idx] = s[threadIdx.x] - v;
    if (threadIdx.x == 1023) bsum[r * NCHUNK + c] = s[1023];
}

__global__ void k_scanB(int* __restrict__ bsum) {
    int r = threadIdx.x;
    if (r >= NREL) return;
    int run = 0;
    for (int c = 0; c < NCHUNK; c++) {
        int v = bsum[r * NCHUNK + c];
        bsum[r * NCHUNK + c] = run;
        run += v;
    }
}

__global__ void k_scanC(int* __restrict__ off, const int* __restrict__ bsum) {
    int r = blockIdx.x / NCHUNK;
    int c = blockIdx.x % NCHUNK;
    int idx = c * 1024 + threadIdx.x;
    if (idx < NNODES) off[r * NNODES + idx] += bsum[r * NCHUNK + c];
}

__global__ void k_fill(const int* __restrict__ src, const int* __restrict__ dst,
                       const int* __restrict__ off, int* __restrict__ cursor,
                       int* __restrict__ lists) {
    int i = blockIdx.x * blockDim.x + threadIdx.x;
    if (i >= NREL * NEDGES) return;
    int r = i / NEDGES;
    int d = dst[i];
    int pos = atomicAdd(&cursor[r * NNODES + d], 1);
    lists[(size_t)r * NEDGES + off[r * NNODES + d] + pos] = src[i];
}

// ---------------------------------------------------------------------------
// fp16 HMMA GEMM: C_z = A @ W_z ; 1 MMA per k-step.
// BM=128 BN=256 BK=32, 256 threads, warp tile 64x64 (2x4 warp grid),
// 2-stage cp.async, 1 CTA/SM (acc regs), crossbar-optimal 128B/MMA.
// z==0 -> fp32 + bias into C0; z>=1 -> fp16 into plane z-1 of Cn
// ---------------------------------------------------------------------------
#define GBM 128
#define GBN 256
#define GBK 32
#define SA_STRIDE 40
#define SB_STRIDE 264
#define SA_STAGE (128 * SA_STRIDE * 2)       // 10240
#define SB_STAGE (32 * SB_STRIDE * 2)        // 16896
#define NSTAGE 2
#define SA_BYTES (NSTAGE * SA_STAGE)
#define GEMM_SMEM (NSTAGE * (SA_STAGE + SB_STAGE))   // 54272

__device__ __forceinline__ void ldsm_x4(uint32_t* r, uint32_t addr) {
    asm volatile("ldmatrix.sync.aligned.m8n8.x4.shared.b16 {%0,%1,%2,%3}, [%4];"
                 : "=r"(r[0]), "=r"(r[1]), "=r"(r[2]), "=r"(r[3]) : "r"(addr));
}
__device__ __forceinline__ void ldsm_x4t(uint32_t* r, uint32_t addr) {
    asm volatile("ldmatrix.sync.aligned.m8n8.x4.trans.shared.b16 {%0,%1,%2,%3}, [%4];"
                 : "=r"(r[0]), "=r"(r[1]), "=r"(r[2]), "=r"(r[3]) : "r"(addr));
}
__device__ __forceinline__ void mma_f16(float* c, const uint32_t* a, const uint32_t* b) {
    asm volatile(
        "mma.sync.aligned.m16n8k16.row.col.f32.f16.f16.f32 "
        "{%0,%1,%2,%3}, {%4,%5,%6,%7}, {%8,%9}, {%0,%1,%2,%3};"
        : "+f"(c[0]), "+f"(c[1]), "+f"(c[2]), "+f"(c[3])
        : "r"(a[0]), "r"(a[1]), "r"(a[2]), "r"(a[3]), "r"(b[0]), "r"(b[1]));
}

__global__ void __launch_bounds__(256, 1) k_mma(
    const __half* __restrict__ A,
    const __half* __restrict__ W_base,
    float* __restrict__ C0, __half* __restrict__ Cn_base,
    const float* __restrict__ bias,
    int M, int N, int K, size_t wstride, size_t cplane_n)
{
    extern __shared__ __align__(16) char smem_raw[];
    const int tid  = threadIdx.x;
    const int lane = tid & 31;
    const int warp = tid >> 5;
    const int bm   = blockIdx.y * GBM;
    const int bn   = blockIdx.x * GBN;
    const int m_base = (warp & 1) * 64;
    const int n_base = (warp >> 1) * 64;

    const __half* Wp = W_base + (size_t)blockIdx.z * wstride;

    const uint32_t sA_u = (uint32_t)__cvta_generic_to_shared(smem_raw);
    const uint32_t sB_u = (uint32_t)__cvta_generic_to_shared(smem_raw + SA_BYTES);

    auto load_tile = [&](int kt, int st) {
        const int k0 = kt * GBK;
        // A: 512 x 16B chunks (row=c>>2, colc=c&3)
#pragma unroll
        for (int i = 0; i < 2; i++) {
            int c = tid + i * 256;
            int row = c >> 2, colc = c & 3;
            int rg = bm + row;
            int rc = (rg < M) ? rg : (M - 1);
            uint32_t dst = sA_u + st * SA_STAGE + (row * SA_STRIDE + colc * 8) * 2;
            asm volatile("cp.async.cg.shared.global [%0], [%1], 16;"
                         :: "r"(dst), "l"(A + (size_t)rc * K + k0 + colc * 8));
        }
        // W: 1024 x 16B chunks (row=c>>5, col16=c&31)
#pragma unroll
        for (int i = 0; i < 4; i++) {
            int c = tid + i * 256;
            int row = c >> 5, col16 = c & 31;
            uint32_t dst = sB_u + st * SB_STAGE + (row * SB_STRIDE + col16 * 8) * 2;
            asm volatile("cp.async.cg.shared.global [%0], [%1], 16;"
                         :: "r"(dst), "l"(Wp + (size_t)(k0 + row) * N + bn + col16 * 8));
        }
    };

    float acc[4][8][4];
#pragma unroll
    for (int i = 0; i < 4; i++)
#pragma unroll
        for (int j = 0; j < 8; j++)
#pragma unroll
            for (int k = 0; k < 4; k++) acc[i][j][k] = 0.0f;

    const int KT = K >> 5;

    load_tile(0, 0);
    asm volatile("cp.async.commit_group;");

    for (int kt = 0; kt < KT; kt++) {
        const int st = kt & 1;
        asm volatile("cp.async.wait_group 0;");
        __syncthreads();
        if (kt + 1 < KT) {
            load_tile(kt + 1, (kt + 1) & 1);
            asm volatile("cp.async.commit_group;");
        }

#pragma unroll
        for (int ks = 0; ks < 2; ks++) {
            const int k0s = ks * 16;
            const int arow = m_base + (lane & 15);
            const int acol = k0s + 8 * (lane >> 4);
            const int brow = k0s + (lane & 15);
            const int bcol = n_base + 8 * (lane >> 4);

            uint32_t av[4][4], bq[8][2];
#pragma unroll
            for (int am = 0; am < 4; am++)
                ldsm_x4(av[am], sA_u + st * SA_STAGE
                        + ((arow + am * 16) * SA_STRIDE + acol) * 2);
#pragma unroll
            for (int bp = 0; bp < 4; bp++) {
                uint32_t r[4];
                ldsm_x4t(r, sB_u + st * SB_STAGE
                         + (brow * SB_STRIDE + bcol + bp * 16) * 2);
                bq[bp * 2][0] = r[0]; bq[bp * 2][1] = r[1];
                bq[bp * 2 + 1][0] = r[2]; bq[bp * 2 + 1][1] = r[3];
            }
#pragma unroll
            for (int am = 0; am < 4; am++)
#pragma unroll
                for (int an = 0; an < 8; an++)
                    mma_f16(acc[am][an], av[am], bq[an]);
        }
    }

    if (blockIdx.z == 0) {
#pragma unroll
        for (int am = 0; am < 4; am++) {
#pragma unroll
            for (int an = 0; an < 8; an++) {
                int col = bn + n_base + an * 8 + (lane & 3) * 2;
                float bx = bias[col], by = bias[col + 1];
                int row0 = bm + m_base + am * 16 + (lane >> 2);
                if (row0 < M) {
                    float2 v = make_float2(acc[am][an][0] + bx, acc[am][an][1] + by);
                    *(float2*)&C0[(size_t)row0 * N + col] = v;
                }
                int row1 = row0 + 8;
                if (row1 < M) {
                    float2 v = make_float2(acc[am][an][2] + bx, acc[am][an][3] + by);
                    *(float2*)&C0[(size_t)row1 * N + col] = v;
                }
            }
        }
    } else {
        __half* Cn = Cn_base + (size_t)(blockIdx.z - 1) * cplane_n;
#pragma unroll
        for (int am = 0; am < 4; am++) {
#pragma unroll
            for (int an = 0; an < 8; an++) {
                int col = bn + n_base + an * 8 + (lane & 3) * 2;
                int row0 = bm + m_base + am * 16 + (lane >> 2);
                if (row0 < M) {
                    __half2 v = __floats2half2_rn(acc[am][an][0], acc[am][an][1]);
                    *(__half2*)&Cn[(size_t)row0 * N + col] = v;
                }
                int row1 = row0 + 8;
                if (row1 < M) {
                    __half2 v = __floats2half2_rn(acc[am][an][2], acc[am][an][3]);
                    *(__half2*)&Cn[(size_t)row1 * N + col] = v;
                }
            }
        }
    }
}

// ---------------------------------------------------------------------------
// fused gather (fp16 planes): acc = accbuf[d] + sum_r invdeg*sum Yh_r[src]
// gather1 writes relu -> fp16 Hh; gather2 writes accbuf (out)
// ---------------------------------------------------------------------------
template <int F, int SPLIT>
__global__ void k_gather(const __half* __restrict__ Yh,
                         const int* __restrict__ off, const int* __restrict__ deg,
                         const int* __restrict__ lists,
                         float* __restrict__ accbuf, __half* __restrict__ Hh)
{
    const int d = blockIdx.x;
    const int t = threadIdx.x;
    const size_t plane = (size_t)NNODES * F;
    const size_t base = (size_t)d * F + t * 4;

    float4 acc = *(const float4*)(accbuf + base);   // self+bias from GEMM z=0

#pragma unroll
    for (int r = 0; r < NREL; r++) {
        int dg = deg[r * NNODES + d];
        if (dg == 0) continue;
        int o = off[r * NNODES + d];
        float w = 1.0f / (float)dg;
        const int* lp = lists + (size_t)r * NEDGES + o;
        const __half* Yp = Yh + (size_t)r * plane;
        float4 tmp = make_float4(0.f, 0.f, 0.f, 0.f);
        for (int k = 0; k < dg; k++) {
            int s = lp[k];
            uint2 u = *(const uint2*)(Yp + (size_t)s * F + t * 4);
            float2 f0 = __half22float2(*(__half2*)&u.x);
            float2 f1 = __half22float2(*(__half2*)&u.y);
            tmp.x += f0.x; tmp.y += f0.y; tmp.z += f1.x; tmp.w += f1.y;
        }
        acc.x += w * tmp.x; acc.y += w * tmp.y;
        acc.z += w * tmp.z; acc.w += w * tmp.w;
    }

    if (SPLIT) {
        __half2 h0 = __floats2half2_rn(fmaxf(acc.x, 0.f), fmaxf(acc.y, 0.f));
        __half2 h1 = __floats2half2_rn(fmaxf(acc.z, 0.f), fmaxf(acc.w, 0.f));
        uint2 u;
        u.x = *(uint32_t*)&h0;
        u.y = *(uint32_t*)&h1;
        *(uint2*)(Hh + base) = u;
    } else {
        *(float4*)(accbuf + base) = acc;
    }
}

// ---------------------------------------------------------------------------
// launch
// ---------------------------------------------------------------------------
extern "C" void kernel_launch(void* const* d_in, const int* in_sizes, int n_in,
                              void* d_out, int out_size)
{
    const float* x       = (const float*)d_in[0];
    const float* Wself1  = (const float*)d_in[1];
    const float* Wneigh1 = (const float*)d_in[2];
    const float* b1      = (const float*)d_in[3];
    const float* Wself2  = (const float*)d_in[4];
    const float* Wneigh2 = (const float*)d_in[5];
    const float* b2      = (const float*)d_in[6];
    const void*  esrc    = d_in[7];
    const void*  edst    = d_in[8];
    float*       out     = (float*)d_out;

    float *H1, *bs1, *bs2;
    __half *Yh, *Xh, *Hh, *W;
    int *src32, *dst32, *deg, *off, *cursor, *bsum, *lists;
    cudaGetSymbolAddress((void**)&Yh,     g_Yh);
    cudaGetSymbolAddress((void**)&H1,     g_H1);
    cudaGetSymbolAddress((void**)&bs1,    g_bs1);
    cudaGetSymbolAddress((void**)&bs2,    g_bs2);
    cudaGetSymbolAddress((void**)&src32,  g_src32);
    cudaGetSymbolAddress((void**)&dst32,  g_dst32);
    cudaGetSymbolAddress((void**)&deg,    g_deg);
    cudaGetSymbolAddress((void**)&off,    g_off);
    cudaGetSymbolAddress((void**)&cursor, g_cursor);
    cudaGetSymbolAddress((void**)&bsum,   g_bsum);
    cudaGetSymbolAddress((void**)&lists,  g_lists);
    cudaGetSymbolAddress((void**)&Xh,     g_Xh);
    cudaGetSymbolAddress((void**)&Hh,     g_Hh);
    cudaGetSymbolAddress((void**)&W,      g_W);

    static bool attr_done = false;
    if (!attr_done) {
        cudaFuncSetAttribute(k_mma, cudaFuncAttributeMaxDynamicSharedMemorySize, GEMM_SMEM);
        attr_done = true;
    }

    const int T = 256;
    const int NE = NREL * NEDGES;
    const size_t PL1 = (size_t)NNODES * HIDF;
    const size_t PL2 = (size_t)NNODES * OUTF;
    const int MB = (NNODES + GBM - 1) / GBM;

    // #0 detect, #1 fused prep, #2 weight prep, #3 layer-1 GEMM (ncu target)
    k_detect<<<1, 32>>>((const unsigned*)esrc);
    {
        size_t n = (size_t)NNODES * INF;
        k_prep<<<(unsigned)((n + T - 1) / T), T>>>(esrc, src32, edst, dst32,
                                                   deg, cursor, x, Xh);
    }
    k_sumsplit_all<<<(W_L1_SZ + T - 1) / T, T>>>(Wself1, Wneigh1, b1,
                                                 Wself2, Wneigh2, b2,
                                                 W, bs1, bs2);
    {
        dim3 g(HIDF / GBN, MB, 5);
        k_mma<<<g, T, GEMM_SMEM>>>(Xh, W, H1, Yh, bs1,
                                   NNODES, HIDF, INF, W_L1_SZ, PL1);
    }

    // CSR build
    k_degcount<<<(NE + T - 1) / T, T>>>(dst32, deg);
    k_scanA<<<NREL * NCHUNK, 1024>>>(deg, off, bsum);
    k_scanB<<<1, 32>>>(bsum);
    k_scanC<<<NREL * NCHUNK, 1024>>>(off, bsum);
    k_fill<<<(NE + T - 1) / T, T>>>(src32, dst32, off, cursor, lists);

    // layer-1 fused gather: aggregate + relu -> fp16 Hh
    k_gather<HIDF, 1><<<NNODES, HIDF / 4>>>(Yh, off, deg, lists, H1, Hh);

    // layer-2 GEMM: z=0 writes out directly (bias), z>=1 fp16 planes
    {
        dim3 g(OUTF / GBN, MB, 5);
        k_mma<<<g, T, GEMM_SMEM>>>(Hh, W + W_L2_OFF, out, Yh, bs2,
                                   NNODES, OUTF, HIDF, W_L2_SZ, PL2);
    }

    // layer-2 fused gather into out
    k_gather<OUTF, 0><<<NNODES, OUTF / 4>>>(Yh, off, deg, lists, out, nullptr);
}

// round 17
// speedup vs baseline: 1.1018x; 1.1018x over previous
#include <cuda_runtime.h>
#include <cuda_bf16.h>
#include <cuda_fp16.h>
#include <cstdint>

// Problem constants (fixed by the reference)
#define NNODES 50000
#define NREL   4
#define NEDGES 250000
#define INF    512
#define HIDF   512
#define OUTF   256

#define NCHUNK 49          // ceil(50000/1024)

#define W_L1_SZ (512 * 512)
#define W_L2_SZ (512 * 256)
#define W_L2_OFF (5 * W_L1_SZ)
#define W_TOT (5 * W_L1_SZ + 5 * W_L2_SZ)

// -------- scratch (device globals: no allocation in kernel_launch) --------
__device__ __align__(16) __half g_Yh[(size_t)4 * NNODES * HIDF]; // 4 neighbor planes (fp16)
__device__ __align__(16) float g_H1[(size_t)NNODES * HIDF];      // layer-1 self+bias / acc
__device__ __align__(16) float g_bs1[HIDF];
__device__ __align__(16) float g_bs2[OUTF];
__device__ __align__(16) int   g_src32[NREL * NEDGES];
__device__ __align__(16) int   g_dst32[NREL * NEDGES];
__device__ __align__(16) int   g_deg[NREL * NNODES];
__device__ __align__(16) int   g_off[NREL * NNODES];
__device__ __align__(16) int   g_cursor[NREL * NNODES];
__device__ __align__(16) int   g_bsum[NREL * NCHUNK];
__device__ __align__(16) int   g_lists[NREL * NEDGES];
__device__ int g_is64;

__device__ __align__(16) __half g_Xh[(size_t)NNODES * INF];   // A layer 1 (fp16)
__device__ __align__(16) __half g_Hh[(size_t)NNODES * HIDF];  // A layer 2 (fp16)
__device__ __align__(16) __half g_W[W_TOT];                   // weight planes [K,N], fp16

// ---------------------------------------------------------------------------
// edge dtype detection
// ---------------------------------------------------------------------------
__global__ void k_detect(const unsigned* __restrict__ w) {
    if (threadIdx.x == 0 && blockIdx.x == 0) {
        unsigned acc = 0;
        for (int i = 0; i < 64; i++) acc |= w[2 * i + 1];
        g_is64 = (acc == 0) ? 1 : 0;
    }
}

// fused prep: edge convert + deg/cursor zero + X fp16 convert
__global__ void k_prep(const void* __restrict__ ps, int* __restrict__ os,
                       const void* __restrict__ pd, int* __restrict__ od,
                       int* __restrict__ deg, int* __restrict__ cursor,
                       const float* __restrict__ x, __half* __restrict__ Xh) {
    const int NE = NREL * NEDGES;
    size_t i = (size_t)blockIdx.x * blockDim.x + threadIdx.x;
    if (i < (size_t)NE) {
        if (g_is64) {
            os[i] = (int)((const long long*)ps)[i];
            od[i] = (int)((const long long*)pd)[i];
        } else {
            os[i] = ((const int*)ps)[i];
            od[i] = ((const int*)pd)[i];
        }
    }
    if (i < NREL * NNODES) { deg[i] = 0; cursor[i] = 0; }
    if (i < (size_t)NNODES * INF) {
        Xh[i] = __float2half_rn(x[i]);
    }
}

// both layers' weight prep (planes [K,N] row-major; 0=sum self), plain fp16
__global__ void k_sumsplit_all(const float* __restrict__ Ws1, const float* __restrict__ Wn1,
                               const float* __restrict__ b1,
                               const float* __restrict__ Ws2, const float* __restrict__ Wn2,
                               const float* __restrict__ b2,
                               __half* __restrict__ w,
                               float* __restrict__ bs1, float* __restrict__ bs2) {
    int i = blockIdx.x * blockDim.x + threadIdx.x;
    if (i >= W_L1_SZ) return;
    {
        float s = 0.0f;
#pragma unroll
        for (int r = 0; r < NREL; r++) s += Ws1[(size_t)r * W_L1_SZ + i];
        w[i] = __float2half_rn(s);
#pragma unroll
        for (int r = 0; r < NREL; r++)
            w[(size_t)(1 + r) * W_L1_SZ + i] =
                __float2half_rn(Wn1[(size_t)r * W_L1_SZ + i]);
    }
    if (i < W_L2_SZ) {
        float s = 0.0f;
#pragma unroll
        for (int r = 0; r < NREL; r++) s += Ws2[(size_t)r * W_L2_SZ + i];
        w[W_L2_OFF + i] = __float2half_rn(s);
#pragma unroll
        for (int r = 0; r < NREL; r++)
            w[W_L2_OFF + (size_t)(1 + r) * W_L2_SZ + i] =
                __float2half_rn(Wn2[(size_t)r * W_L2_SZ + i]);
    }
    if (i < HIDF) {
        float bb = 0.0f;
#pragma unroll
        for (int r = 0; r < NREL; r++) bb += b1[r * HIDF + i];
        bs1[i] = bb;
    }
    if (i < OUTF) {
        float bb = 0.0f;
#pragma unroll
        for (int r = 0; r < NREL; r++) bb += b2[r * OUTF + i];
        bs2[i] = bb;
    }
}

// ---------------------------------------------------------------------------
// CSR build
// ---------------------------------------------------------------------------
__global__ void k_degcount(const int* __restrict__ dst, int* __restrict__ deg) {
    int i = blockIdx.x * blockDim.x + threadIdx.x;
    if (i >= NREL * NEDGES) return;
    int r = i / NEDGES;
    atomicAdd(&deg[r * NNODES + dst[i]], 1);
}

__global__ void k_scanA(const int* __restrict__ deg, int* __restrict__ off,
                        int* __restrict__ bsum) {
    __shared__ int s[1024];
    int r = blockIdx.x / NCHUNK;
    int c = blockIdx.x % NCHUNK;
    int idx = c * 1024 + threadIdx.x;
    int v = (idx < NNODES) ? deg[r * NNODES + idx] : 0;
    s[threadIdx.x] = v;
    __syncthreads();
#pragma unroll
    for (int d = 1; d < 1024; d <<= 1) {
        int t = (threadIdx.x >= d) ? s[threadIdx.x - d] : 0;
        __syncthreads();
        s[threadIdx.x] += t;
        __syncthreads();
    }
    if (idx < NNODES) off[r * NNODES + idx] = s[threadIdx.x] - v;
    if (threadIdx.x == 1023) bsum[r * NCHUNK + c] = s[1023];
}

__global__ void k_scanB(int* __restrict__ bsum) {
    int r = threadIdx.x;
    if (r >= NREL) return;
    int run = 0;
    for (int c = 0; c < NCHUNK; c++) {
        int v = bsum[r * NCHUNK + c];
        bsum[r * NCHUNK + c] = run;
        run += v;
    }
}

__global__ void k_scanC(int* __restrict__ off, const int* __restrict__ bsum) {
    int r = blockIdx.x / NCHUNK;
    int c = blockIdx.x % NCHUNK;
    int idx = c * 1024 + threadIdx.x;
    if (idx < NNODES) off[r * NNODES + idx] += bsum[r * NCHUNK + c];
}

__global__ void k_fill(const int* __restrict__ src, const int* __restrict__ dst,
                       const int* __restrict__ off, int* __restrict__ cursor,
                       int* __restrict__ lists) {
    int i = blockIdx.x * blockDim.x + threadIdx.x;
    if (i >= NREL * NEDGES) return;
    int r = i / NEDGES;
    int d = dst[i];
    int pos = atomicAdd(&cursor[r * NNODES + d], 1);
    lists[(size_t)r * NEDGES + off[r * NNODES + d] + pos] = src[i];
}

// ---------------------------------------------------------------------------
// fp16 HMMA GEMM: C_z = A @ W_z ; 1 MMA per k-step.
// BM=128 BN=128 BK=64, 256 threads, warp tile 64x32, 2-stage, 2 CTAs/SM.
// z==0 -> fp32 + bias into C0; z>=1 -> fp16 into plane z-1 of Cn
// ---------------------------------------------------------------------------
#define GBM 128
#define GBN 128
#define GBK 64
#define SA_STRIDE 72
#define SB_STRIDE 136
#define SA_STAGE (128 * SA_STRIDE * 2)       // 18432
#define SB_STAGE (64 * SB_STRIDE * 2)        // 17408
#define NSTAGE 2
#define SA_BYTES (NSTAGE * SA_STAGE)
#define GEMM_SMEM (NSTAGE * (SA_STAGE + SB_STAGE))   // 71680 (x2 CTA = 143360)

__device__ __forceinline__ void ldsm_x4(uint32_t* r, uint32_t addr) {
    asm volatile("ldmatrix.sync.aligned.m8n8.x4.shared.b16 {%0,%1,%2,%3}, [%4];"
                 : "=r"(r[0]), "=r"(r[1]), "=r"(r[2]), "=r"(r[3]) : "r"(addr));
}
__device__ __forceinline__ void ldsm_x4t(uint32_t* r, uint32_t addr) {
    asm volatile("ldmatrix.sync.aligned.m8n8.x4.trans.shared.b16 {%0,%1,%2,%3}, [%4];"
                 : "=r"(r[0]), "=r"(r[1]), "=r"(r[2]), "=r"(r[3]) : "r"(addr));
}
__device__ __forceinline__ void mma_f16(float* c, const uint32_t* a, const uint32_t* b) {
    asm volatile(
        "mma.sync.aligned.m16n8k16.row.col.f32.f16.f16.f32 "
        "{%0,%1,%2,%3}, {%4,%5,%6,%7}, {%8,%9}, {%0,%1,%2,%3};"
        : "+f"(c[0]), "+f"(c[1]), "+f"(c[2]), "+f"(c[3])
        : "r"(a[0]), "r"(a[1]), "r"(a[2]), "r"(a[3]), "r"(b[0]), "r"(b[1]));
}

__global__ void __launch_bounds__(256, 2) k_mma(
    const __half* __restrict__ A,
    const __half* __restrict__ W_base,
    float* __restrict__ C0, __half* __restrict__ Cn_base,
    const float* __restrict__ bias,
    int M, int N, int K, size_t wstride, size_t cplane_n)
{
    extern __shared__ __align__(16) char smem_raw[];
    const int tid  = threadIdx.x;
    const int lane = tid & 31;
    const int warp = tid >> 5;
    const int bm   = blockIdx.y * GBM;
    const int bn   = blockIdx.x * GBN;
    const int m_base = (warp & 1) * 64;
    const int n_base = (warp >> 1) * 32;

    const __half* Wp = W_base + (size_t)blockIdx.z * wstride;

    const uint32_t sA_u = (uint32_t)__cvta_generic_to_shared(smem_raw);
    const uint32_t sB_u = (uint32_t)__cvta_generic_to_shared(smem_raw + SA_BYTES);

    auto load_tile = [&](int kt, int st) {
        const int k0 = kt * GBK;
        // A: 128 rows x 64 cols = 1024 x 16B chunks (row=c>>3, colc=c&7)
#pragma unroll
        for (int i = 0; i < 4; i++) {
            int c = tid + i * 256;
            int row = c >> 3, colc = c & 7;
            int rg = bm + row;
            int rc = (rg < M) ? rg : (M - 1);
            uint32_t dst = sA_u + st * SA_STAGE + (row * SA_STRIDE + colc * 8) * 2;
            asm volatile("cp.async.cg.shared.global [%0], [%1], 16;"
                         :: "r"(dst), "l"(A + (size_t)rc * K + k0 + colc * 8));
        }
        // W: 64 rows x 128 cols = 1024 x 16B chunks (row=c>>4, col16=c&15)
#pragma unroll
        for (int i = 0; i < 4; i++) {
            int c = tid + i * 256;
            int row = c >> 4, col16 = c & 15;
            uint32_t dst = sB_u + st * SB_STAGE + (row * SB_STRIDE + col16 * 8) * 2;
            asm volatile("cp.async.cg.shared.global [%0], [%1], 16;"
                         :: "r"(dst), "l"(Wp + (size_t)(k0 + row) * N + bn + col16 * 8));
        }
    };

    float acc[4][4][4];
#pragma unroll
    for (int i = 0; i < 4; i++)
#pragma unroll
        for (int j = 0; j < 4; j++)
#pragma unroll
            for (int k = 0; k < 4; k++) acc[i][j][k] = 0.0f;

    const int KT = K / GBK;

    load_tile(0, 0);
    asm volatile("cp.async.commit_group;");

    for (int kt = 0; kt < KT; kt++) {
        const int st = kt & 1;
        asm volatile("cp.async.wait_group 0;");
        __syncthreads();
        if (kt + 1 < KT) {
            load_tile(kt + 1, (kt + 1) & 1);
            asm volatile("cp.async.commit_group;");
        }

#pragma unroll
        for (int ks = 0; ks < 4; ks++) {
            const int k0s = ks * 16;
            const int arow = m_base + (lane & 15);
            const int acol = k0s + 8 * (lane >> 4);
            const int brow = k0s + (lane & 15);
            const int bcol = n_base + 8 * (lane >> 4);

            uint32_t av[4][4], bq[4][2];
#pragma unroll
            for (int am = 0; am < 4; am++)
                ldsm_x4(av[am], sA_u + st * SA_STAGE
                        + ((arow + am * 16) * SA_STRIDE + acol) * 2);
            {
                uint32_t r[4];
                ldsm_x4t(r, sB_u + st * SB_STAGE + (brow * SB_STRIDE + bcol) * 2);
                bq[0][0] = r[0]; bq[0][1] = r[1]; bq[1][0] = r[2]; bq[1][1] = r[3];
                ldsm_x4t(r, sB_u + st * SB_STAGE + (brow * SB_STRIDE + bcol + 16) * 2);
                bq[2][0] = r[0]; bq[2][1] = r[1]; bq[3][0] = r[2]; bq[3][1] = r[3];
            }
#pragma unroll
            for (int am = 0; am < 4; am++)
#pragma unroll
                for (int an = 0; an < 4; an++)
                    mma_f16(acc[am][an], av[am], bq[an]);
        }
    }

    if (blockIdx.z == 0) {
#pragma unroll
        for (int am = 0; am < 4; am++) {
#pragma unroll
            for (int an = 0; an < 4; an++) {
                int col = bn + n_base + an * 8 + (lane & 3) * 2;
                float bx = bias[col], by = bias[col + 1];
                int row0 = bm + m_base + am * 16 + (lane >> 2);
                if (row0 < M) {
                    float2 v = make_float2(acc[am][an][0] + bx, acc[am][an][1] + by);
                    *(float2*)&C0[(size_t)row0 * N + col] = v;
                }
                int row1 = row0 + 8;
                if (row1 < M) {
                    float2 v = make_float2(acc[am][an][2] + bx, acc[am][an][3] + by);
                    *(float2*)&C0[(size_t)row1 * N + col] = v;
                }
            }
        }
    } else {
        __half* Cn = Cn_base + (size_t)(blockIdx.z - 1) * cplane_n;
#pragma unroll
        for (int am = 0; am < 4; am++) {
#pragma unroll
            for (int an = 0; an < 4; an++) {
                int col = bn + n_base + an * 8 + (lane & 3) * 2;
                int row0 = bm + m_base + am * 16 + (lane >> 2);
                if (row0 < M) {
                    __half2 v = __floats2half2_rn(acc[am][an][0], acc[am][an][1]);
                    *(__half2*)&Cn[(size_t)row0 * N + col] = v;
                }
                int row1 = row0 + 8;
                if (row1 < M) {
                    __half2 v = __floats2half2_rn(acc[am][an][2], acc[am][an][3]);
                    *(__half2*)&Cn[(size_t)row1 * N + col] = v;
                }
            }
        }
    }
}

// ---------------------------------------------------------------------------
// fused gather (fp16 planes): acc = accbuf[d] + sum_r invdeg*sum Yh_r[src]
// gather1 writes relu -> fp16 Hh; gather2 writes accbuf (out)
// ---------------------------------------------------------------------------
template <int F, int SPLIT>
__global__ void k_gather(const __half* __restrict__ Yh,
                         const int* __restrict__ off, const int* __restrict__ deg,
                         const int* __restrict__ lists,
                         float* __restrict__ accbuf, __half* __restrict__ Hh)
{
    const int d = blockIdx.x;
    const int t = threadIdx.x;
    const size_t plane = (size_t)NNODES * F;
    const size_t base = (size_t)d * F + t * 4;

    float4 acc = *(const float4*)(accbuf + base);   // self+bias from GEMM z=0

#pragma unroll
    for (int r = 0; r < NREL; r++) {
        int dg = deg[r * NNODES + d];
        if (dg == 0) continue;
        int o = off[r * NNODES + d];
        float w = 1.0f / (float)dg;
        const int* lp = lists + (size_t)r * NEDGES + o;
        const __half* Yp = Yh + (size_t)r * plane;
        float4 tmp = make_float4(0.f, 0.f, 0.f, 0.f);
        for (int k = 0; k < dg; k++) {
            int s = lp[k];
            uint2 u = *(const uint2*)(Yp + (size_t)s * F + t * 4);
            float2 f0 = __half22float2(*(__half2*)&u.x);
            float2 f1 = __half22float2(*(__half2*)&u.y);
            tmp.x += f0.x; tmp.y += f0.y; tmp.z += f1.x; tmp.w += f1.y;
        }
        acc.x += w * tmp.x; acc.y += w * tmp.y;
        acc.z += w * tmp.z; acc.w += w * tmp.w;
    }

    if (SPLIT) {
        __half2 h0 = __floats2half2_rn(fmaxf(acc.x, 0.f), fmaxf(acc.y, 0.f));
        __half2 h1 = __floats2half2_rn(fmaxf(acc.z, 0.f), fmaxf(acc.w, 0.f));
        uint2 u;
        u.x = *(uint32_t*)&h0;
        u.y = *(uint32_t*)&h1;
        *(uint2*)(Hh + base) = u;
    } else {
        *(float4*)(accbuf + base) = acc;
    }
}

// ---------------------------------------------------------------------------
// launch
// ---------------------------------------------------------------------------
extern "C" void kernel_launch(void* const* d_in, const int* in_sizes, int n_in,
                              void* d_out, int out_size)
{
    const float* x       = (const float*)d_in[0];
    const float* Wself1  = (const float*)d_in[1];
    const float* Wneigh1 = (const float*)d_in[2];
    const float* b1      = (const float*)d_in[3];
    const float* Wself2  = (const float*)d_in[4];
    const float* Wneigh2 = (const float*)d_in[5];
    const float* b2      = (const float*)d_in[6];
    const void*  esrc    = d_in[7];
    const void*  edst    = d_in[8];
    float*       out     = (float*)d_out;

    float *H1, *bs1, *bs2;
    __half *Yh, *Xh, *Hh, *W;
    int *src32, *dst32, *deg, *off, *cursor, *bsum, *lists;
    cudaGetSymbolAddress((void**)&Yh,     g_Yh);
    cudaGetSymbolAddress((void**)&H1,     g_H1);
    cudaGetSymbolAddress((void**)&bs1,    g_bs1);
    cudaGetSymbolAddress((void**)&bs2,    g_bs2);
    cudaGetSymbolAddress((void**)&src32,  g_src32);
    cudaGetSymbolAddress((void**)&dst32,  g_dst32);
    cudaGetSymbolAddress((void**)&deg,    g_deg);
    cudaGetSymbolAddress((void**)&off,    g_off);
    cudaGetSymbolAddress((void**)&cursor, g_cursor);
    cudaGetSymbolAddress((void**)&bsum,   g_bsum);
    cudaGetSymbolAddress((void**)&lists,  g_lists);
    cudaGetSymbolAddress((void**)&Xh,     g_Xh);
    cudaGetSymbolAddress((void**)&Hh,     g_Hh);
    cudaGetSymbolAddress((void**)&W,      g_W);

    static bool attr_done = false;
    if (!attr_done) {
        cudaFuncSetAttribute(k_mma, cudaFuncAttributeMaxDynamicSharedMemorySize, GEMM_SMEM);
        attr_done = true;
    }

    const int T = 256;
    const int NE = NREL * NEDGES;
    const size_t PL1 = (size_t)NNODES * HIDF;
    const size_t PL2 = (size_t)NNODES * OUTF;
    const int MB = (NNODES + GBM - 1) / GBM;

    // #0 detect, #1 fused prep, #2 weight prep, #3 layer-1 GEMM (ncu target)
    k_detect<<<1, 32>>>((const unsigned*)esrc);
    {
        size_t n = (size_t)NNODES * INF;
        k_prep<<<(unsigned)((n + T - 1) / T), T>>>(esrc, src32, edst, dst32,
                                                   deg, cursor, x, Xh);
    }
    k_sumsplit_all<<<(W_L1_SZ + T - 1) / T, T>>>(Wself1, Wneigh1, b1,
                                                 Wself2, Wneigh2, b2,
                                                 W, bs1, bs2);
    {
        dim3 g(HIDF / GBN, MB, 5);
        k_mma<<<g, T, GEMM_SMEM>>>(Xh, W, H1, Yh, bs1,
                                   NNODES, HIDF, INF, W_L1_SZ, PL1);
    }

    // CSR build
    k_degcount<<<(NE + T - 1) / T, T>>>(dst32, deg);
    k_scanA<<<NREL * NCHUNK, 1024>>>(deg, off, bsum);
    k_scanB<<<1, 32>>>(bsum);
    k_scanC<<<NREL * NCHUNK, 1024>>>(off, bsum);
    k_fill<<<(NE + T - 1) / T, T>>>(src32, dst32, off, cursor, lists);

    // layer-1 fused gather: aggregate + relu -> fp16 Hh
    k_gather<HIDF, 1><<<NNODES, HIDF / 4>>>(Yh, off, deg, lists, H1, Hh);

    // layer-2 GEMM: z=0 writes out directly (bias), z>=1 fp16 planes
    {
        dim3 g(OUTF / GBN, MB, 5);
        k_mma<<<g, T, GEMM_SMEM>>>(Hh, W + W_L2_OFF, out, Yh, bs2,
                                   NNODES, OUTF, HIDF, W_L2_SZ, PL2);
    }

    // layer-2 fused gather into out
    k_gather<OUTF, 0><<<NNODES, OUTF / 4>>>(Yh, off, deg, lists, out, nullptr);
}